// round 5
// baseline (speedup 1.0000x reference)
#include <cuda_runtime.h>
#include <cuda_bf16.h>
#include <math_constants.h>

#define HIDDEN 1024
#define MAX_SUBWORDS 8192

__device__ float g_scores[MAX_SUBWORDS];

// Kernel 1: scores[s] = dot(hidden[s], w). One warp per subword row.
// (Bias skipped: softmax is shift-invariant.)
__global__ void __launch_bounds__(256) scores_kernel(
        const float* __restrict__ hs,
        const float* __restrict__ w_attn,
        int n_sub) {
    int warp = (blockIdx.x * blockDim.x + threadIdx.x) >> 5;
    int lane = threadIdx.x & 31;
    if (warp >= n_sub) return;

    const float4* row = reinterpret_cast<const float4*>(hs + (size_t)warp * HIDDEN);
    const float4* wv  = reinterpret_cast<const float4*>(w_attn);

    float acc = 0.0f;
#pragma unroll
    for (int i = 0; i < HIDDEN / 128; i++) {   // 8 independent float4 loads -> MLP 8
        float4 a = row[lane + i * 32];
        float4 c = wv[lane + i * 32];
        acc += a.x * c.x + a.y * c.y + a.z * c.z + a.w * c.w;
    }
#pragma unroll
    for (int o = 16; o > 0; o >>= 1)
        acc += __shfl_xor_sync(0xFFFFFFFFu, acc, o);

    if (lane == 0) g_scores[warp] = acc;
}

// Kernel 2: one WARP per word. Each lane owns 8 float4 columns (32 floats),
// giving 8 independent loads in flight per span row (MLP=8 per latency chain).
// Softmax is shifted by the first score: row s0 enters with weight exp(0)=1,
// so the accumulator is seeded by a plain row read and length-1 spans are a
// pure copy.
__global__ void __launch_bounds__(128) pool_kernel(
        const float* __restrict__ hs,
        const void*  __restrict__ starts_raw,
        const void*  __restrict__ ends_raw,
        float*       __restrict__ out,
        int n_words, int n_sub) {
    int gw   = (blockIdx.x * blockDim.x + threadIdx.x) >> 5;   // word index
    int lane = threadIdx.x & 31;
    if (gw >= n_words) return;

    // dtype sniff (warp-local, no smem): int64-LE values (<2^31) have zero
    // odd int32 words. 32 genuine sorted int32 starts can't all be zero there.
    const int* pr = (const int*)starts_raw;
    int nchk = n_words < 64 ? (n_words >> 1) : 32;
    int zero = (lane >= nchk) || (pr[2 * lane + 1] == 0);
    bool is64 = (__ballot_sync(0xFFFFFFFFu, zero) == 0xFFFFFFFFu);

    int s0, s1;
    if (is64) {
        s0 = (int)((const long long*)starts_raw)[gw];
        s1 = (int)((const long long*)ends_raw)[gw];
    } else {
        s0 = ((const int*)starts_raw)[gw];
        s1 = ((const int*)ends_raw)[gw];
    }
    s0 = max(0, min(s0, n_sub - 1));
    s1 = max(s0, min(s1, n_sub - 1));

    // Seed accumulator with row s0 (weight exp(score[s0]-score[s0]) = 1).
    float4 acc[8];
    {
        const float4* r0 = reinterpret_cast<const float4*>(hs + (size_t)s0 * HIDDEN);
#pragma unroll
        for (int i = 0; i < 8; i++) acc[i] = r0[lane + 32 * i];
    }

    float4* op = reinterpret_cast<float4*>(out + (size_t)gw * HIDDEN);

    if (s1 > s0) {
        float ref = g_scores[s0];
        float Z = 1.0f;
        for (int s = s0 + 1; s <= s1; s++) {
            float p = __expf(g_scores[s] - ref);
            Z += p;
            const float4* rv = reinterpret_cast<const float4*>(hs + (size_t)s * HIDDEN);
#pragma unroll
            for (int i = 0; i < 8; i++) {
                float4 v = rv[lane + 32 * i];
                acc[i].x += p * v.x;
                acc[i].y += p * v.y;
                acc[i].z += p * v.z;
                acc[i].w += p * v.w;
            }
        }
        float inv = 1.0f / Z;
#pragma unroll
        for (int i = 0; i < 8; i++) {
            acc[i].x *= inv; acc[i].y *= inv; acc[i].z *= inv; acc[i].w *= inv;
        }
    }

#pragma unroll
    for (int i = 0; i < 8; i++) op[lane + 32 * i] = acc[i];
}

extern "C" void kernel_launch(void* const* d_in, const int* in_sizes, int n_in,
                              void* d_out, int out_size) {
    const float* hs     = (const float*)d_in[0];   // [n_sub, 1024]
    const void*  starts = d_in[1];                 // [n_words] int32 or int64
    const void*  ends   = d_in[2];                 // [n_words]
    const float* w_attn = (const float*)d_in[3];   // [1024, 1]
    float*       out    = (float*)d_out;           // [n_words, 1024]

    int n_sub   = in_sizes[0] / HIDDEN;
    int n_words = in_sizes[1];

    scores_kernel<<<(n_sub + 7) / 8, 256>>>(hs, w_attn, n_sub);

    // 4 warps (words) per block.
    pool_kernel<<<(n_words + 3) / 4, 128>>>(hs, starts, ends, out, n_words, n_sub);
}

// round 6
// speedup vs baseline: 1.1212x; 1.1212x over previous
#include <cuda_runtime.h>
#include <cuda_bf16.h>
#include <math_constants.h>

#define HIDDEN 1024
#define MAX_SUBWORDS 8192
#define MAX_WORDS    8192
#define CONV_BLOCKS  8

__device__ float g_scores[MAX_SUBWORDS];
__device__ int   g_starts[MAX_WORDS];
__device__ int   g_ends[MAX_WORDS];

// Kernel 1: (a) scores[s] = dot(hidden[s], w), one warp per row (bias skipped:
// softmax is shift-invariant); (b) trailing CONV_BLOCKS blocks sniff the index
// dtype and convert+clamp spans into int32 device arrays, overlapped with (a).
__global__ void __launch_bounds__(256) scores_conv_kernel(
        const float* __restrict__ hs,
        const float* __restrict__ w_attn,
        const void*  __restrict__ starts_raw,
        const void*  __restrict__ ends_raw,
        int n_sub, int n_words, int row_blocks) {
    if ((int)blockIdx.x >= row_blocks) {
        // ---- index conversion blocks ----
        int cid  = blockIdx.x - row_blocks;
        int lane = threadIdx.x & 31;
        // dtype sniff (warp-local ballot): int64-LE values (<2^31) have zero
        // odd int32 words; 32 genuine sorted int32 starts can't all be 0 there.
        const int* pr = (const int*)starts_raw;
        int nchk = n_words < 64 ? (n_words >> 1) : 32;
        int zero = (lane >= nchk) || (pr[2 * lane + 1] == 0);
        bool is64 = (__ballot_sync(0xFFFFFFFFu, zero) == 0xFFFFFFFFu);

        int stride = CONV_BLOCKS * blockDim.x;
        for (int i = cid * blockDim.x + threadIdx.x; i < n_words; i += stride) {
            int a, b;
            if (is64) {
                a = (int)((const long long*)starts_raw)[i];
                b = (int)((const long long*)ends_raw)[i];
            } else {
                a = ((const int*)starts_raw)[i];
                b = ((const int*)ends_raw)[i];
            }
            a = max(0, min(a, n_sub - 1));
            b = max(a, min(b, n_sub - 1));
            g_starts[i] = a;
            g_ends[i]   = b;
        }
        return;
    }

    // ---- score blocks: one warp per subword row ----
    int warp = (blockIdx.x * blockDim.x + threadIdx.x) >> 5;
    int lane = threadIdx.x & 31;
    if (warp >= n_sub) return;

    const float4* row = reinterpret_cast<const float4*>(hs + (size_t)warp * HIDDEN);
    const float4* wv  = reinterpret_cast<const float4*>(w_attn);

    float acc = 0.0f;
#pragma unroll
    for (int i = 0; i < HIDDEN / 128; i++) {
        float4 a = row[lane + i * 32];
        float4 c = wv[lane + i * 32];
        acc += a.x * c.x + a.y * c.y + a.z * c.z + a.w * c.w;
    }
#pragma unroll
    for (int o = 16; o > 0; o >>= 1)
        acc += __shfl_xor_sync(0xFFFFFFFFu, acc, o);

    if (lane == 0) g_scores[warp] = acc;
}

// Kernel 2: one 64-thread block per word; thread t owns 4 float4 columns
// (t, t+64, t+128, t+192). Small blocks -> ~25 resident blocks/SM, so many
// independent idx->row latency chains overlap. Softmax shifted by the first
// score: row s0 seeds the accumulator at weight 1; length-1 spans are a copy.
__global__ void __launch_bounds__(64) pool_kernel(
        const float* __restrict__ hs,
        float* __restrict__ out,
        int n_words) {
    int w = blockIdx.x;
    if (w >= n_words) return;
    int t = threadIdx.x;   // 0..63

    int s0 = g_starts[w];
    int s1 = g_ends[w];

    float4 acc[4];
    {
        const float4* r0 = reinterpret_cast<const float4*>(hs + (size_t)s0 * HIDDEN);
#pragma unroll
        for (int i = 0; i < 4; i++) acc[i] = r0[t + 64 * i];
    }

    if (s1 > s0) {
        float ref = g_scores[s0];
        float Z = 1.0f;
        for (int s = s0 + 1; s <= s1; s++) {
            float p = __expf(g_scores[s] - ref);
            Z += p;
            const float4* rv = reinterpret_cast<const float4*>(hs + (size_t)s * HIDDEN);
#pragma unroll
            for (int i = 0; i < 4; i++) {
                float4 v = rv[t + 64 * i];
                acc[i].x += p * v.x;
                acc[i].y += p * v.y;
                acc[i].z += p * v.z;
                acc[i].w += p * v.w;
            }
        }
        float inv = 1.0f / Z;
#pragma unroll
        for (int i = 0; i < 4; i++) {
            acc[i].x *= inv; acc[i].y *= inv; acc[i].z *= inv; acc[i].w *= inv;
        }
    }

    float4* op = reinterpret_cast<float4*>(out + (size_t)w * HIDDEN);
#pragma unroll
    for (int i = 0; i < 4; i++) op[t + 64 * i] = acc[i];
}

extern "C" void kernel_launch(void* const* d_in, const int* in_sizes, int n_in,
                              void* d_out, int out_size) {
    const float* hs     = (const float*)d_in[0];   // [n_sub, 1024]
    const void*  starts = d_in[1];                 // [n_words] int32 or int64
    const void*  ends   = d_in[2];                 // [n_words]
    const float* w_attn = (const float*)d_in[3];   // [1024, 1]
    float*       out    = (float*)d_out;           // [n_words, 1024]

    int n_sub   = in_sizes[0] / HIDDEN;
    int n_words = in_sizes[1];

    int row_blocks = (n_sub + 7) / 8;              // 8 warps (rows) per block
    scores_conv_kernel<<<row_blocks + CONV_BLOCKS, 256>>>(
        hs, w_attn, starts, ends, n_sub, n_words, row_blocks);

    pool_kernel<<<n_words, 64>>>(hs, out, n_words);
}

// round 7
// speedup vs baseline: 1.2786x; 1.1404x over previous
#include <cuda_runtime.h>
#include <cuda_bf16.h>
#include <math_constants.h>

#define HIDDEN 1024
#define MAX_SUBWORDS 8192
#define MAX_WORDS    8192
#define CONV_BLOCKS  8
#define WPB          8     // words per pool block

__device__ float g_scores[MAX_SUBWORDS];
__device__ int   g_starts[MAX_WORDS];
__device__ int   g_ends[MAX_WORDS];

// Kernel 1: (a) scores[s] = dot(hidden[s], w), one warp per row (bias skipped:
// softmax is shift-invariant); (b) trailing CONV_BLOCKS blocks sniff the index
// dtype and convert+clamp spans into int32 device arrays, overlapped with (a).
__global__ void __launch_bounds__(256) scores_conv_kernel(
        const float* __restrict__ hs,
        const float* __restrict__ w_attn,
        const void*  __restrict__ starts_raw,
        const void*  __restrict__ ends_raw,
        int n_sub, int n_words, int row_blocks) {
    if ((int)blockIdx.x >= row_blocks) {
        // ---- index conversion blocks ----
        int cid  = blockIdx.x - row_blocks;
        int lane = threadIdx.x & 31;
        // dtype sniff (warp ballot): int64-LE values (<2^31) have zero odd
        // int32 words; 32 genuine sorted int32 starts can't all be 0 there.
        const int* pr = (const int*)starts_raw;
        int nchk = n_words < 64 ? (n_words >> 1) : 32;
        int zero = (lane >= nchk) || (pr[2 * lane + 1] == 0);
        bool is64 = (__ballot_sync(0xFFFFFFFFu, zero) == 0xFFFFFFFFu);

        int stride = CONV_BLOCKS * blockDim.x;
        for (int i = cid * blockDim.x + threadIdx.x; i < n_words; i += stride) {
            int a, b;
            if (is64) {
                a = (int)((const long long*)starts_raw)[i];
                b = (int)((const long long*)ends_raw)[i];
            } else {
                a = ((const int*)starts_raw)[i];
                b = ((const int*)ends_raw)[i];
            }
            a = max(0, min(a, n_sub - 1));
            b = max(a, min(b, n_sub - 1));
            g_starts[i] = a;
            g_ends[i]   = b;
        }
        return;
    }

    // ---- score blocks: one warp per subword row ----
    int warp = (blockIdx.x * blockDim.x + threadIdx.x) >> 5;
    int lane = threadIdx.x & 31;
    if (warp >= n_sub) return;

    const float4* row = reinterpret_cast<const float4*>(hs + (size_t)warp * HIDDEN);
    const float4* wv  = reinterpret_cast<const float4*>(w_attn);

    float acc = 0.0f;
#pragma unroll
    for (int i = 0; i < HIDDEN / 128; i++) {
        float4 a = row[lane + i * 32];
        float4 c = wv[lane + i * 32];
        acc += a.x * c.x + a.y * c.y + a.z * c.z + a.w * c.w;
    }
#pragma unroll
    for (int o = 16; o > 0; o >>= 1)
        acc += __shfl_xor_sync(0xFFFFFFFFu, acc, o);

    if (lane == 0) g_scores[warp] = acc;
}

// Kernel 2: word-chunked streaming pool. Each 256-thread block handles WPB
// consecutive words; thread t owns float4 column t of the whole row. Words in
// a chunk touch consecutive hs rows -> near-sequential load stream, and loads
// for word w+1 are independent of word w's accumulator, so the LSU stays full.
// Softmax shifted by the first score: row s0 seeds acc at weight exp(0)=1;
// length-1 spans are a pure copy (no score loads at all).
__global__ void __launch_bounds__(256) pool_kernel(
        const float* __restrict__ hs,
        float* __restrict__ out,
        int n_words) {
    int t     = threadIdx.x;                 // 0..255, float4 column
    int wbase = blockIdx.x * WPB;
    int wend  = min(wbase + WPB, n_words);

    for (int w = wbase; w < wend; w++) {
        int s0 = g_starts[w];
        int s1 = g_ends[w];

        float4 acc = reinterpret_cast<const float4*>(hs + (size_t)s0 * HIDDEN)[t];

        if (s1 > s0) {
            float ref = g_scores[s0];        // broadcast, L1-resident
            float Z = 1.0f;
            for (int s = s0 + 1; s <= s1; s++) {
                float p = __expf(g_scores[s] - ref);
                Z += p;
                float4 v = reinterpret_cast<const float4*>(hs + (size_t)s * HIDDEN)[t];
                acc.x += p * v.x;
                acc.y += p * v.y;
                acc.z += p * v.z;
                acc.w += p * v.w;
            }
            float inv = 1.0f / Z;
            acc.x *= inv; acc.y *= inv; acc.z *= inv; acc.w *= inv;
        }

        reinterpret_cast<float4*>(out + (size_t)w * HIDDEN)[t] = acc;
    }
}

extern "C" void kernel_launch(void* const* d_in, const int* in_sizes, int n_in,
                              void* d_out, int out_size) {
    const float* hs     = (const float*)d_in[0];   // [n_sub, 1024]
    const void*  starts = d_in[1];                 // [n_words] int32 or int64
    const void*  ends   = d_in[2];                 // [n_words]
    const float* w_attn = (const float*)d_in[3];   // [1024, 1]
    float*       out    = (float*)d_out;           // [n_words, 1024]

    int n_sub   = in_sizes[0] / HIDDEN;
    int n_words = in_sizes[1];

    int row_blocks = (n_sub + 7) / 8;              // 8 warps (rows) per block
    scores_conv_kernel<<<row_blocks + CONV_BLOCKS, 256>>>(
        hs, w_attn, starts, ends, n_sub, n_words, row_blocks);

    pool_kernel<<<(n_words + WPB - 1) / WPB, 256>>>(hs, out, n_words);
}